// round 7
// baseline (speedup 1.0000x reference)
#include <cuda_runtime.h>
#include <cuda_bf16.h>
#include <math.h>
#include <stdint.h>

// Problem constants
#define B_   2
#define S_   2048
#define D_   1024
#define H_   16
#define DK_  64
#define MTOT (B_ * S_)   // 4096
#define WSZ  ((size_t)D_ * D_)

// bf16 hi/lo buffers
__device__ __nv_bfloat16 g_xhi[(size_t)MTOT * D_];
__device__ __nv_bfloat16 g_xlo[(size_t)MTOT * D_];
__device__ __nv_bfloat16 g_whi[4][WSZ];
__device__ __nv_bfloat16 g_wlo[4][WSZ];
__device__ __nv_bfloat16 g_qhi[(size_t)MTOT * D_];
__device__ __nv_bfloat16 g_qlo[(size_t)MTOT * D_];
__device__ __nv_bfloat16 g_khi[(size_t)MTOT * D_];
__device__ __nv_bfloat16 g_klo[(size_t)MTOT * D_];
__device__ __nv_bfloat16 g_vhi[(size_t)MTOT * D_];
__device__ __nv_bfloat16 g_vlo[(size_t)MTOT * D_];
__device__ __nv_bfloat16 g_ohi[(size_t)MTOT * D_];
__device__ __nv_bfloat16 g_olo[(size_t)MTOT * D_];

// ============================================================================
// PTX helpers (base sm_100-safe)
// ============================================================================
__device__ __forceinline__ uint32_t smem_u32(const void* p) {
    return (uint32_t)__cvta_generic_to_shared(p);
}

#define CP_ASYNC16(dst, src) \
    asm volatile("cp.async.cg.shared.global [%0], [%1], 16;" :: "r"(dst), "l"(src))
#define CP_COMMIT() asm volatile("cp.async.commit_group;")
#define CP_WAIT1()  asm volatile("cp.async.wait_group 1;")
#define CP_WAIT0()  asm volatile("cp.async.wait_group 0;")

#define LDSM_X4(r, addr)                                                     \
    asm volatile("ldmatrix.sync.aligned.m8n8.x4.shared.b16 {%0,%1,%2,%3}, [%4];" \
                 : "=r"((r)[0]), "=r"((r)[1]), "=r"((r)[2]), "=r"((r)[3])    \
                 : "r"(addr))

#define LDSM_X4_T(r, addr)                                                   \
    asm volatile("ldmatrix.sync.aligned.m8n8.x4.trans.shared.b16 {%0,%1,%2,%3}, [%4];" \
                 : "=r"((r)[0]), "=r"((r)[1]), "=r"((r)[2]), "=r"((r)[3])    \
                 : "r"(addr))

#define MMA16816(d, a, b0v, b1v)                                             \
    asm volatile("mma.sync.aligned.m16n8k16.row.col.f32.bf16.bf16.f32 "     \
                 "{%0,%1,%2,%3}, {%4,%5,%6,%7}, {%8,%9}, {%0,%1,%2,%3};"    \
                 : "+f"((d)[0]), "+f"((d)[1]), "+f"((d)[2]), "+f"((d)[3])   \
                 : "r"((a)[0]), "r"((a)[1]), "r"((a)[2]), "r"((a)[3]),      \
                   "r"(b0v), "r"(b1v))

// split a,b into bf16 hi pair + lo pair
__device__ __forceinline__ void split_pack(float a, float b, uint32_t& hi, uint32_t& lo) {
    __nv_bfloat162 h = __floats2bfloat162_rn(a, b);
    float2 hf = __bfloat1622float2(h);
    __nv_bfloat162 l = __floats2bfloat162_rn(a - hf.x, b - hf.y);
    hi = *(uint32_t*)&h;
    lo = *(uint32_t*)&l;
}

// ============================================================================
// hi/lo bf16 split kernels
// ============================================================================
__device__ __forceinline__ void split4(const float* __restrict__ src,
                                       __nv_bfloat16* __restrict__ hi,
                                       __nv_bfloat16* __restrict__ lo, int i)
{
    float4 v = *(const float4*)(src + i);
    uint32_t h0, l0, h1, l1;
    split_pack(v.x, v.y, h0, l0);
    split_pack(v.z, v.w, h1, l1);
    uint2 hh = make_uint2(h0, h1), ll = make_uint2(l0, l1);
    *(uint2*)(hi + i) = hh;
    *(uint2*)(lo + i) = ll;
}

__global__ void split_bf16(const float* __restrict__ src,
                           __nv_bfloat16* __restrict__ hi,
                           __nv_bfloat16* __restrict__ lo, int n)
{
    int i = (blockIdx.x * blockDim.x + threadIdx.x) * 4;
    if (i < n) split4(src, hi, lo, i);
}

__global__ void split_w4(const float* __restrict__ W0, const float* __restrict__ W1,
                         const float* __restrict__ W2, const float* __restrict__ W3,
                         __nv_bfloat16* __restrict__ hiB, __nv_bfloat16* __restrict__ loB)
{
    const int z = blockIdx.z;
    const float* src = (z == 0) ? W0 : (z == 1) ? W1 : (z == 2) ? W2 : W3;
    int i = (blockIdx.x * blockDim.x + threadIdx.x) * 4;
    split4(src, hiB + z * WSZ, loB + z * WSZ, i);
}

// ============================================================================
// mma.sync GEMM v3: C = A @ W^T + bias  (3-term bf16 split)
// CTA 64x128, 8 warps 2(m)x4(n), warp tile 32x32, BK=32, 3-stage pipeline.
// MMAs issued TERM-MAJOR: same-accumulator reuse distance 8 (was 1) so warp
// issue runs at throughput, not HMMA latency.
// ============================================================================
#define GBK     32
#define G_AHI   0u
#define G_ALO   4096u
#define G_WHI   8192u
#define G_WLO   16384u
#define G_STAGE 24576u
#define GSM_BYTES (3 * 24576 + 128)   // 73856

__global__ __launch_bounds__(256, 2) void gemm_mma(
    const __nv_bfloat16* __restrict__ Ahi, const __nv_bfloat16* __restrict__ Alo,
    const __nv_bfloat16* __restrict__ WhB, const __nv_bfloat16* __restrict__ WlB,
    int wofs,
    const float* __restrict__ b0, const float* __restrict__ b1, const float* __restrict__ b2,
    float* __restrict__ Cf,
    __nv_bfloat16* __restrict__ C0h, __nv_bfloat16* __restrict__ C0l,
    __nv_bfloat16* __restrict__ C1h, __nv_bfloat16* __restrict__ C1l,
    __nv_bfloat16* __restrict__ C2h, __nv_bfloat16* __restrict__ C2l,
    float s0, int mode)
{
    extern __shared__ char dsm[];
    const uint32_t smbase = (smem_u32(dsm) + 127u) & ~127u;

    const int tid  = threadIdx.x;
    const int lane = tid & 31;
    const int wid  = tid >> 5;
    const int wm   = wid >> 2;      // 0..1
    const int wn   = wid & 3;       // 0..3
    const int row0 = blockIdx.y * 64;
    const int col0 = blockIdx.x * 128;
    const int z    = blockIdx.z;

    const __nv_bfloat16* Whi = WhB + (size_t)(wofs + z) * WSZ;
    const __nv_bfloat16* Wlo = WlB + (size_t)(wofs + z) * WSZ;
    const float* bias = (z == 0) ? b0 : (z == 1) ? b1 : b2;
    __nv_bfloat16* Chi = (z == 0) ? C0h : (z == 1) ? C1h : C2h;
    __nv_bfloat16* Clo = (z == 0) ? C0l : (z == 1) ? C1l : C2l;
    const float scale = (z == 0) ? s0 : 1.0f;

    const __nv_bfloat16* srcs[4] = {
        Ahi + (size_t)row0 * D_, Alo + (size_t)row0 * D_,
        Whi + (size_t)col0 * D_, Wlo + (size_t)col0 * D_
    };

    // loader mapping: 1536 granules/stage (A:256+256, W:512+512), 6/thread
    int l_mat[6], l_r[6], l_koff[6];
    uint32_t l_dst[6];
    #pragma unroll
    for (int t = 0; t < 6; t++) {
        int idx = tid + t * 256;
        int mat, i;
        uint32_t base, chunk;
        if (idx < 512) {
            mat = idx >> 8; i = idx & 255;
            base = (uint32_t)mat * 4096u; chunk = 2048u;
        } else {
            mat = 2 + ((idx - 512) >> 9); i = (idx - 512) & 511;
            base = 8192u + (uint32_t)(mat - 2) * 8192u; chunk = 4096u;
        }
        int r = i >> 2, kk = (i >> 1) & 1, g = i & 1;
        int gsw = g ^ ((r >> 2) & 1);
        l_mat[t] = mat; l_r[t] = r; l_koff[t] = kk * 16 + g * 8;
        l_dst[t] = base + (uint32_t)kk * chunk + (uint32_t)r * 32u + (uint32_t)gsw * 16u;
    }

    auto issue = [&](int it2) {
        const uint32_t sb = smbase + (uint32_t)(it2 % 3) * G_STAGE;
        #pragma unroll
        for (int t = 0; t < 6; t++) {
            const __nv_bfloat16* gp = srcs[l_mat[t]] +
                (size_t)l_r[t] * D_ + it2 * GBK + l_koff[t];
            CP_ASYNC16(sb + l_dst[t], gp);
        }
    };

    float acc[2][4][4];
    #pragma unroll
    for (int mi = 0; mi < 2; mi++)
        #pragma unroll
        for (int nj = 0; nj < 4; nj++)
            #pragma unroll
            for (int e = 0; e < 4; e++) acc[mi][nj][e] = 0.0f;

    const int lr = lane & 15;
    const int lg = lane >> 4;

    issue(0); CP_COMMIT();
    issue(1); CP_COMMIT();

    const int NIT = D_ / GBK;   // 32
    for (int it = 0; it < NIT; it++) {
        if (it < NIT - 1) { CP_WAIT1(); } else { CP_WAIT0(); }
        __syncthreads();
        if (it + 2 < NIT) { issue(it + 2); CP_COMMIT(); }

        const uint32_t stg = smbase + (uint32_t)(it % 3) * G_STAGE;
        #pragma unroll
        for (int kk = 0; kk < 2; kk++) {
            uint32_t a_hi[2][4], a_lo[2][4];
            #pragma unroll
            for (int mi = 0; mi < 2; mi++) {
                int r = wm * 32 + mi * 16 + lr;
                uint32_t off = (uint32_t)(kk * 2048 + r * 32 + ((lg ^ ((r >> 2) & 1)) * 16));
                LDSM_X4(a_hi[mi], stg + G_AHI + off);
                LDSM_X4(a_lo[mi], stg + G_ALO + off);
            }
            uint32_t b_hi[2][4], b_lo[2][4];
            #pragma unroll
            for (int ni = 0; ni < 2; ni++) {
                int r = wn * 32 + ni * 16 + lr;
                uint32_t off = (uint32_t)(kk * 4096 + r * 32 + ((lg ^ ((r >> 2) & 1)) * 16));
                LDSM_X4(b_hi[ni], stg + G_WHI + off);
                LDSM_X4(b_lo[ni], stg + G_WLO + off);
            }
            // ---- TERM-MAJOR: 8 independent accs between same-acc reuses ----
            #pragma unroll
            for (int mi = 0; mi < 2; mi++)
                #pragma unroll
                for (int nj = 0; nj < 4; nj++) {
                    const int ni = nj >> 1, sel = nj & 1;
                    MMA16816(acc[mi][nj], a_hi[mi], b_hi[ni][sel], b_hi[ni][sel + 2]);
                }
            #pragma unroll
            for (int mi = 0; mi < 2; mi++)
                #pragma unroll
                for (int nj = 0; nj < 4; nj++) {
                    const int ni = nj >> 1, sel = nj & 1;
                    MMA16816(acc[mi][nj], a_hi[mi], b_lo[ni][sel], b_lo[ni][sel + 2]);
                }
            #pragma unroll
            for (int mi = 0; mi < 2; mi++)
                #pragma unroll
                for (int nj = 0; nj < 4; nj++) {
                    const int ni = nj >> 1, sel = nj & 1;
                    MMA16816(acc[mi][nj], a_lo[mi], b_hi[ni][sel], b_hi[ni][sel + 2]);
                }
        }
    }

    const int qr = lane >> 2;
    const int qc = (lane & 3) * 2;
    #pragma unroll
    for (int nj = 0; nj < 4; nj++) {
        const int c = col0 + wn * 32 + nj * 8 + qc;
        const float2 bv = *(const float2*)(bias + c);
        #pragma unroll
        for (int mi = 0; mi < 2; mi++) {
            const int r = row0 + wm * 32 + mi * 16 + qr;
            float v0 = acc[mi][nj][0] + bv.x, v1 = acc[mi][nj][1] + bv.y;
            float v2 = acc[mi][nj][2] + bv.x, v3 = acc[mi][nj][3] + bv.y;
            if (mode == 0) {
                *(float2*)(Cf + (size_t)r * D_ + c)       = make_float2(v0, v1);
                *(float2*)(Cf + (size_t)(r + 8) * D_ + c) = make_float2(v2, v3);
            } else {
                v0 *= scale; v1 *= scale; v2 *= scale; v3 *= scale;
                uint32_t h0, l0, h1, l1;
                split_pack(v0, v1, h0, l0);
                split_pack(v2, v3, h1, l1);
                *(uint32_t*)(Chi + (size_t)r * D_ + c)       = h0;
                *(uint32_t*)(Clo + (size_t)r * D_ + c)       = l0;
                *(uint32_t*)(Chi + (size_t)(r + 8) * D_ + c) = h1;
                *(uint32_t*)(Clo + (size_t)(r + 8) * D_ + c) = l1;
            }
        }
    }
}

// ============================================================================
// Tensor-core flash attention v3 (causal), 3-term bf16 split.
// Same structure as v2; MMA issue reordered to alternate accumulators
// (same-acc distance 2 instead of 1) in both QK and PV blocks.
// ============================================================================
#define FQ    128
#define FKT   64
#define F_KHI 0
#define F_KLO 8192
#define F_VHI 16384
#define F_VLO 24576
#define F_STG 32768
#define F_QLO (2 * F_STG)               // persistent Q-lo region (16KB)
#define FSM_BYTES (2 * F_STG + 16384 + 128)

__global__ __launch_bounds__(256, 2) void flash_mma(
    const __nv_bfloat16* __restrict__ Qhi, const __nv_bfloat16* __restrict__ Qlo,
    const __nv_bfloat16* __restrict__ Khi, const __nv_bfloat16* __restrict__ Klo,
    const __nv_bfloat16* __restrict__ Vhi, const __nv_bfloat16* __restrict__ Vlo,
    __nv_bfloat16* __restrict__ Ohi, __nv_bfloat16* __restrict__ Olo)
{
    extern __shared__ char dsm[];
    const uint32_t smbase = (smem_u32(dsm) + 127u) & ~127u;

    const int tid  = threadIdx.x;
    const int lane = tid & 31;
    const int w    = tid >> 5;
    const int qb   = (int)gridDim.x - 1 - (int)blockIdx.x;  // big tiles first
    const int h    = blockIdx.y;
    const int b    = blockIdx.z;
    const int q0   = qb * FQ;

    // ---- stage Q: hi -> stage0 (temp), lo -> persistent region
    #pragma unroll
    for (int t = 0; t < 4; t++) {
        int idx = tid + t * 256;
        int row = idx >> 3, g = idx & 7;
        const __nv_bfloat16* src = Qhi + (size_t)(b * S_ + q0 + row) * D_ + h * DK_ + g * 8;
        CP_ASYNC16(smbase + row * 128 + ((g ^ (row & 7)) << 4), src);
    }
    #pragma unroll
    for (int t = 0; t < 4; t++) {
        int idx = tid + t * 256;
        int row = idx >> 3, g = idx & 7;
        const __nv_bfloat16* src = Qlo + (size_t)(b * S_ + q0 + row) * D_ + h * DK_ + g * 8;
        CP_ASYNC16(smbase + F_QLO + row * 128 + ((g ^ (row & 7)) << 4), src);
    }
    CP_COMMIT();
    CP_WAIT0();
    __syncthreads();

    uint32_t qa_h[4][4];
    const int qrow = w * 16 + (lane & 15);
    const int qlg  = lane >> 4;
    #pragma unroll
    for (int c = 0; c < 4; c++) {
        uint32_t off = qrow * 128 + ((c * 32 + qlg * 16) ^ ((qrow & 7) << 4));
        LDSM_X4(qa_h[c], smbase + off);
    }
    __syncthreads();   // stage0 free for KV

    const __nv_bfloat16* kvsrc[4] = {Khi, Klo, Vhi, Vlo};
    auto load_kv = [&](int t) {
        const uint32_t stg = smbase + (uint32_t)(t & 1) * F_STG;
        #pragma unroll
        for (int u = 0; u < 8; u++) {
            int idx = tid + u * 256;
            int mat = idx >> 9;
            int i   = idx & 511;
            int row = i >> 3, g = i & 7;
            const __nv_bfloat16* src = kvsrc[mat] +
                (size_t)(b * S_ + t * FKT + row) * D_ + h * DK_ + g * 8;
            CP_ASYNC16(stg + mat * 8192 + row * 128 + ((g ^ (row & 7)) << 4), src);
        }
    };

    const int nkt = 2 * (qb + 1);
    load_kv(0); CP_COMMIT();
    if (nkt > 1) { load_kv(1); CP_COMMIT(); }

    float m_r[2] = {-1e30f, -1e30f};
    float l_r[2] = {0.0f, 0.0f};
    float oacc[8][4];
    #pragma unroll
    for (int j = 0; j < 8; j++)
        #pragma unroll
        for (int e = 0; e < 4; e++) oacc[j][e] = 0.0f;

    const int rg0 = q0 + w * 16 + (lane >> 2);

    for (int t = 0; t < nkt; t++) {
        if (t + 1 < nkt) { CP_WAIT1(); } else { CP_WAIT0(); }
        __syncthreads();

        const uint32_t stg = smbase + (uint32_t)(t & 1) * F_STG;

        // ---- scores S = Q K^T, 3-term split, alternating accumulators
        float sacc[8][4];
        #pragma unroll
        for (int j = 0; j < 8; j++)
            #pragma unroll
            for (int e = 0; e < 4; e++) sacc[j][e] = 0.0f;

        #pragma unroll
        for (int c = 0; c < 4; c++) {
            uint32_t qa_l[4];
            {
                uint32_t off = qrow * 128 + ((c * 32 + qlg * 16) ^ ((qrow & 7) << 4));
                LDSM_X4(qa_l, smbase + F_QLO + off);
            }
            #pragma unroll
            for (int ng = 0; ng < 4; ng++) {
                int row = ng * 16 + (lane & 15);
                int colb = c * 32 + qlg * 16;
                uint32_t off = row * 128 + (colb ^ ((row & 7) << 4));
                uint32_t kh[4], kl[4];
                LDSM_X4(kh, stg + F_KHI + off);
                LDSM_X4(kl, stg + F_KLO + off);
                const int j0 = ng * 2, j1 = ng * 2 + 1;
                MMA16816(sacc[j0], qa_h[c], kh[0], kh[2]);
                MMA16816(sacc[j1], qa_h[c], kh[1], kh[3]);
                MMA16816(sacc[j0], qa_h[c], kl[0], kl[2]);
                MMA16816(sacc[j1], qa_h[c], kl[1], kl[3]);
                MMA16816(sacc[j0], qa_l,    kh[0], kh[2]);
                MMA16816(sacc[j1], qa_l,    kh[1], kh[3]);
            }
        }

        // ---- causal mask
        const int kt0 = t * FKT;
        if (kt0 + FKT - 1 > q0 + w * 16) {
            #pragma unroll
            for (int j = 0; j < 8; j++) {
                int kc = kt0 + j * 8 + (lane & 3) * 2;
                if (kc     > rg0)     sacc[j][0] = -1e30f;
                if (kc + 1 > rg0)     sacc[j][1] = -1e30f;
                if (kc     > rg0 + 8) sacc[j][2] = -1e30f;
                if (kc + 1 > rg0 + 8) sacc[j][3] = -1e30f;
            }
        }

        // ---- online softmax
        float tm0 = -1e30f, tm1 = -1e30f;
        #pragma unroll
        for (int j = 0; j < 8; j++) {
            tm0 = fmaxf(tm0, fmaxf(sacc[j][0], sacc[j][1]));
            tm1 = fmaxf(tm1, fmaxf(sacc[j][2], sacc[j][3]));
        }
        tm0 = fmaxf(tm0, __shfl_xor_sync(0xffffffffu, tm0, 1));
        tm0 = fmaxf(tm0, __shfl_xor_sync(0xffffffffu, tm0, 2));
        tm1 = fmaxf(tm1, __shfl_xor_sync(0xffffffffu, tm1, 1));
        tm1 = fmaxf(tm1, __shfl_xor_sync(0xffffffffu, tm1, 2));

        float mn0 = fmaxf(m_r[0], tm0);
        float mn1 = fmaxf(m_r[1], tm1);
        float a0 = __expf(m_r[0] - mn0);
        float a1 = __expf(m_r[1] - mn1);
        m_r[0] = mn0; m_r[1] = mn1;

        float ps0 = 0.0f, ps1 = 0.0f;
        #pragma unroll
        for (int j = 0; j < 8; j++) {
            sacc[j][0] = __expf(sacc[j][0] - mn0);
            sacc[j][1] = __expf(sacc[j][1] - mn0);
            sacc[j][2] = __expf(sacc[j][2] - mn1);
            sacc[j][3] = __expf(sacc[j][3] - mn1);
            ps0 += sacc[j][0] + sacc[j][1];
            ps1 += sacc[j][2] + sacc[j][3];
        }
        ps0 += __shfl_xor_sync(0xffffffffu, ps0, 1);
        ps0 += __shfl_xor_sync(0xffffffffu, ps0, 2);
        ps1 += __shfl_xor_sync(0xffffffffu, ps1, 1);
        ps1 += __shfl_xor_sync(0xffffffffu, ps1, 2);
        l_r[0] = l_r[0] * a0 + ps0;
        l_r[1] = l_r[1] * a1 + ps1;

        #pragma unroll
        for (int j = 0; j < 8; j++) {
            oacc[j][0] *= a0; oacc[j][1] *= a0;
            oacc[j][2] *= a1; oacc[j][3] *= a1;
        }

        // ---- PV: oacc += P @ V, 3-term split, alternating accumulators
        #pragma unroll
        for (int tk = 0; tk < 4; tk++) {
            uint32_t pah[4], pal[4];
            split_pack(sacc[2*tk][0],   sacc[2*tk][1],   pah[0], pal[0]);
            split_pack(sacc[2*tk][2],   sacc[2*tk][3],   pah[1], pal[1]);
            split_pack(sacc[2*tk+1][0], sacc[2*tk+1][1], pah[2], pal[2]);
            split_pack(sacc[2*tk+1][2], sacc[2*tk+1][3], pah[3], pal[3]);

            #pragma unroll
            for (int dp = 0; dp < 4; dp++) {
                int sub = lane >> 3, i8 = lane & 7;
                int row = tk * 16 + (sub & 1) * 8 + i8;
                int colb = dp * 32 + (sub >> 1) * 16;
                uint32_t off = row * 128 + (colb ^ ((row & 7) << 4));
                uint32_t vh[4], vl[4];
                LDSM_X4_T(vh, stg + F_VHI + off);
                LDSM_X4_T(vl, stg + F_VLO + off);
                const int j0 = dp * 2, j1 = dp * 2 + 1;
                MMA16816(oacc[j0], pah, vh[0], vh[1]);
                MMA16816(oacc[j1], pah, vh[2], vh[3]);
                MMA16816(oacc[j0], pah, vl[0], vl[1]);
                MMA16816(oacc[j1], pah, vl[2], vl[3]);
                MMA16816(oacc[j0], pal, vh[0], vh[1]);
                MMA16816(oacc[j1], pal, vh[2], vh[3]);
            }
        }
        __syncthreads();          // all warps done with stage (t&1)
        if (t + 2 < nkt) { load_kv(t + 2); CP_COMMIT(); }
    }

    // ---- epilogue
    const float inv0 = 1.0f / l_r[0];
    const float inv1 = 1.0f / l_r[1];
    const size_t r0 = (size_t)(b * S_) + rg0;
    const size_t r1 = r0 + 8;
    #pragma unroll
    for (int j = 0; j < 8; j++) {
        int col = h * DK_ + j * 8 + (lane & 3) * 2;
        uint32_t h0, l0, h1, l1;
        split_pack(oacc[j][0] * inv0, oacc[j][1] * inv0, h0, l0);
        split_pack(oacc[j][2] * inv1, oacc[j][3] * inv1, h1, l1);
        *(uint32_t*)(Ohi + r0 * D_ + col) = h0;
        *(uint32_t*)(Olo + r0 * D_ + col) = l0;
        *(uint32_t*)(Ohi + r1 * D_ + col) = h1;
        *(uint32_t*)(Olo + r1 * D_ + col) = l1;
    }
}

// ============================================================================
// Launch
// ============================================================================
extern "C" void kernel_launch(void* const* d_in, const int* in_sizes, int n_in,
                              void* d_out, int out_size)
{
    const float* X  = (const float*)d_in[0];
    const float* Wq = (const float*)d_in[1];
    const float* bq = (const float*)d_in[2];
    const float* Wk = (const float*)d_in[3];
    const float* bk = (const float*)d_in[4];
    const float* Wv = (const float*)d_in[5];
    const float* bv = (const float*)d_in[6];
    const float* Wo = (const float*)d_in[7];
    const float* bo = (const float*)d_in[8];
    float* out = (float*)d_out;

    __nv_bfloat16 *xhi, *xlo, *whi, *wlo;
    __nv_bfloat16 *qhi, *qlo, *khi, *klo, *vhi, *vlo, *ohi, *olo;
    cudaGetSymbolAddress((void**)&xhi, g_xhi);
    cudaGetSymbolAddress((void**)&xlo, g_xlo);
    cudaGetSymbolAddress((void**)&whi, g_whi);
    cudaGetSymbolAddress((void**)&wlo, g_wlo);
    cudaGetSymbolAddress((void**)&qhi, g_qhi);
    cudaGetSymbolAddress((void**)&qlo, g_qlo);
    cudaGetSymbolAddress((void**)&khi, g_khi);
    cudaGetSymbolAddress((void**)&klo, g_klo);
    cudaGetSymbolAddress((void**)&vhi, g_vhi);
    cudaGetSymbolAddress((void**)&vlo, g_vlo);
    cudaGetSymbolAddress((void**)&ohi, g_ohi);
    cudaGetSymbolAddress((void**)&olo, g_olo);

    cudaFuncSetAttribute(gemm_mma, cudaFuncAttributeMaxDynamicSharedMemorySize, GSM_BYTES);
    cudaFuncSetAttribute(flash_mma, cudaFuncAttributeMaxDynamicSharedMemorySize, FSM_BYTES);

    const int nX = MTOT * D_;
    const int nW = D_ * D_;

    split_bf16<<<nX / 1024, 256>>>(X, xhi, xlo, nX);
    split_w4<<<dim3(nW / 1024, 1, 4), 256>>>(Wq, Wk, Wv, Wo, whi, wlo);

    // fused QKV projection (z = 0:Q, 1:K, 2:V); Q pre-scaled by 1/sqrt(dk)
    gemm_mma<<<dim3(8, 64, 3), 256, GSM_BYTES>>>(
        xhi, xlo, whi, wlo, 0, bq, bk, bv,
        nullptr, qhi, qlo, khi, klo, vhi, vlo, 0.125f, 1);

    flash_mma<<<dim3(S_ / FQ, H_, B_), 256, FSM_BYTES>>>(qhi, qlo, khi, klo,
                                                         vhi, vlo, ohi, olo);

    // O projection (fp32 out)
    gemm_mma<<<dim3(8, 64, 1), 256, GSM_BYTES>>>(
        ohi, olo, whi, wlo, 3, bo, bo, bo,
        out, nullptr, nullptr, nullptr, nullptr, nullptr, nullptr, 1.0f, 0);
}

// round 8
// speedup vs baseline: 1.3740x; 1.3740x over previous
#include <cuda_runtime.h>
#include <cuda_fp16.h>
#include <math.h>
#include <stdint.h>

// Problem constants
#define B_   2
#define S_   2048
#define D_   1024
#define H_   16
#define DK_  64
#define MTOT (B_ * S_)   // 4096
#define WSZ  ((size_t)D_ * D_)

#define WSCALE   64.0f
#define INV_WS   (1.0f / 64.0f)

// fp16 buffers: A-side single, B-side hi/lo
__device__ __half g_xf [(size_t)MTOT * D_];     // X  (A-side, single)
__device__ __half g_wh [4][WSZ];                // 64*W hi
__device__ __half g_wl [4][WSZ];                // 64*W lo
__device__ __half g_qf [(size_t)MTOT * D_];     // Q  (A-side, single, pre-scaled)
__device__ __half g_kh [(size_t)MTOT * D_];
__device__ __half g_kl [(size_t)MTOT * D_];
__device__ __half g_vh [(size_t)MTOT * D_];
__device__ __half g_vl [(size_t)MTOT * D_];
__device__ __half g_of [(size_t)MTOT * D_];     // attn out (A-side, single)

// ============================================================================
// PTX helpers (base sm_100-safe)
// ============================================================================
__device__ __forceinline__ uint32_t smem_u32(const void* p) {
    return (uint32_t)__cvta_generic_to_shared(p);
}

#define CP_ASYNC16(dst, src) \
    asm volatile("cp.async.cg.shared.global [%0], [%1], 16;" :: "r"(dst), "l"(src))
#define CP_COMMIT() asm volatile("cp.async.commit_group;")
#define CP_WAIT1()  asm volatile("cp.async.wait_group 1;")
#define CP_WAIT0()  asm volatile("cp.async.wait_group 0;")

#define LDSM_X4(r, addr)                                                     \
    asm volatile("ldmatrix.sync.aligned.m8n8.x4.shared.b16 {%0,%1,%2,%3}, [%4];" \
                 : "=r"((r)[0]), "=r"((r)[1]), "=r"((r)[2]), "=r"((r)[3])    \
                 : "r"(addr))

#define LDSM_X4_T(r, addr)                                                   \
    asm volatile("ldmatrix.sync.aligned.m8n8.x4.trans.shared.b16 {%0,%1,%2,%3}, [%4];" \
                 : "=r"((r)[0]), "=r"((r)[1]), "=r"((r)[2]), "=r"((r)[3])    \
                 : "r"(addr))

#define MMAH16816(d, a, b0v, b1v)                                            \
    asm volatile("mma.sync.aligned.m16n8k16.row.col.f32.f16.f16.f32 "       \
                 "{%0,%1,%2,%3}, {%4,%5,%6,%7}, {%8,%9}, {%0,%1,%2,%3};"    \
                 : "+f"((d)[0]), "+f"((d)[1]), "+f"((d)[2]), "+f"((d)[3])   \
                 : "r"((a)[0]), "r"((a)[1]), "r"((a)[2]), "r"((a)[3]),      \
                   "r"(b0v), "r"(b1v))

__device__ __forceinline__ uint32_t pack_h2(float a, float b) {
    __half2 h = __floats2half2_rn(a, b);
    return *(uint32_t*)&h;
}
// split a,b into fp16 hi pair + lo pair
__device__ __forceinline__ void split_pack_h(float a, float b, uint32_t& hi, uint32_t& lo) {
    __half2 h = __floats2half2_rn(a, b);
    float2 hf = __half22float2(h);
    __half2 l = __floats2half2_rn(a - hf.x, b - hf.y);
    hi = *(uint32_t*)&h;
    lo = *(uint32_t*)&l;
}

// ============================================================================
// conversion kernels
// ============================================================================
__global__ void cvt_half(const float* __restrict__ src, __half* __restrict__ dst, int n)
{
    int i = (blockIdx.x * blockDim.x + threadIdx.x) * 4;
    if (i >= n) return;
    float4 v = *(const float4*)(src + i);
    uint2 o = make_uint2(pack_h2(v.x, v.y), pack_h2(v.z, v.w));
    *(uint2*)(dst + i) = o;
}

// 4-weight split with *WSCALE pre-scaling (z selects which W)
__global__ void split_w4(const float* __restrict__ W0, const float* __restrict__ W1,
                         const float* __restrict__ W2, const float* __restrict__ W3,
                         __half* __restrict__ hiB, __half* __restrict__ loB)
{
    const int z = blockIdx.z;
    const float* src = (z == 0) ? W0 : (z == 1) ? W1 : (z == 2) ? W2 : W3;
    int i = (blockIdx.x * blockDim.x + threadIdx.x) * 4;
    float4 v = *(const float4*)(src + i);
    uint32_t h0, l0, h1, l1;
    split_pack_h(v.x * WSCALE, v.y * WSCALE, h0, l0);
    split_pack_h(v.z * WSCALE, v.w * WSCALE, h1, l1);
    *(uint2*)(hiB + z * WSZ + i) = make_uint2(h0, h1);
    *(uint2*)(loB + z * WSZ + i) = make_uint2(l0, l1);
}

// ============================================================================
// mma.sync GEMM v4: C = A @ W^T + bias   (2-term fp16: A single, W hi/lo)
// CTA 64x128, 8 warps 2(m)x4(n), warp tile 32x32, BK=32, 3-stage pipeline.
// Stage 20KB: A(4KB) | Whi(8KB) | Wlo(8KB).
// ============================================================================
#define GBK     32
#define G_A     0u
#define G_WHI   4096u
#define G_WLO   12288u
#define G_STAGE 20480u
#define GSM_BYTES (3 * 20480 + 128)

__global__ __launch_bounds__(256, 2) void gemm_mma(
    const __half* __restrict__ Af,
    const __half* __restrict__ WhB, const __half* __restrict__ WlB,
    int wofs,
    const float* __restrict__ b0, const float* __restrict__ b1, const float* __restrict__ b2,
    float* __restrict__ Cf,
    __half* __restrict__ Cq,                                   // z==0 single out
    __half* __restrict__ C1h, __half* __restrict__ C1l,        // z==1 hi/lo out
    __half* __restrict__ C2h, __half* __restrict__ C2l,        // z==2 hi/lo out
    float qs, int mode)
{
    extern __shared__ char dsm[];
    const uint32_t smbase = (smem_u32(dsm) + 127u) & ~127u;

    const int tid  = threadIdx.x;
    const int lane = tid & 31;
    const int wid  = tid >> 5;
    const int wm   = wid >> 2;      // 0..1
    const int wn   = wid & 3;       // 0..3
    const int row0 = blockIdx.y * 64;
    const int col0 = blockIdx.x * 128;
    const int z    = blockIdx.z;

    const __half* Whi = WhB + (size_t)(wofs + z) * WSZ;
    const __half* Wlo = WlB + (size_t)(wofs + z) * WSZ;
    const float* bias = (z == 0) ? b0 : (z == 1) ? b1 : b2;
    __half* Chi = (z == 1) ? C1h : C2h;
    __half* Clo = (z == 1) ? C1l : C2l;
    const float scale = (z == 0) ? qs : 1.0f;

    const __half* srcs[3] = {
        Af + (size_t)row0 * D_,
        Whi + (size_t)col0 * D_, Wlo + (size_t)col0 * D_
    };

    // loader: 1280 granules/stage (A:256, Whi:512, Wlo:512) = 5/thread
    int l_mat[5], l_r[5], l_koff[5];
    uint32_t l_dst[5];
    #pragma unroll
    for (int t = 0; t < 5; t++) {
        int idx = tid + t * 256;
        int mat, i;
        uint32_t base, chunk;
        if (idx < 256)       { mat = 0; i = idx;       base = G_A;   chunk = 2048u; }
        else if (idx < 768)  { mat = 1; i = idx - 256; base = G_WHI; chunk = 4096u; }
        else                 { mat = 2; i = idx - 768; base = G_WLO; chunk = 4096u; }
        int r = i >> 2, kk = (i >> 1) & 1, g = i & 1;
        int gsw = g ^ ((r >> 2) & 1);
        l_mat[t] = mat; l_r[t] = r; l_koff[t] = kk * 16 + g * 8;
        l_dst[t] = base + (uint32_t)kk * chunk + (uint32_t)r * 32u + (uint32_t)gsw * 16u;
    }

    auto issue = [&](int it2) {
        const uint32_t sb = smbase + (uint32_t)(it2 % 3) * G_STAGE;
        #pragma unroll
        for (int t = 0; t < 5; t++) {
            const __half* gp = srcs[l_mat[t]] +
                (size_t)l_r[t] * D_ + it2 * GBK + l_koff[t];
            CP_ASYNC16(sb + l_dst[t], gp);
        }
    };

    float acc[2][4][4];
    #pragma unroll
    for (int mi = 0; mi < 2; mi++)
        #pragma unroll
        for (int nj = 0; nj < 4; nj++)
            #pragma unroll
            for (int e = 0; e < 4; e++) acc[mi][nj][e] = 0.0f;

    const int lr = lane & 15;
    const int lg = lane >> 4;

    issue(0); CP_COMMIT();
    issue(1); CP_COMMIT();

    const int NIT = D_ / GBK;   // 32
    for (int it = 0; it < NIT; it++) {
        if (it < NIT - 1) { CP_WAIT1(); } else { CP_WAIT0(); }
        __syncthreads();
        if (it + 2 < NIT) { issue(it + 2); CP_COMMIT(); }

        const uint32_t stg = smbase + (uint32_t)(it % 3) * G_STAGE;
        #pragma unroll
        for (int kk = 0; kk < 2; kk++) {
            uint32_t af[2][4];
            #pragma unroll
            for (int mi = 0; mi < 2; mi++) {
                int r = wm * 32 + mi * 16 + lr;
                uint32_t off = (uint32_t)(kk * 2048 + r * 32 + ((lg ^ ((r >> 2) & 1)) * 16));
                LDSM_X4(af[mi], stg + G_A + off);
            }
            uint32_t b_hi[2][4], b_lo[2][4];
            #pragma unroll
            for (int ni = 0; ni < 2; ni++) {
                int r = wn * 32 + ni * 16 + lr;
                uint32_t off = (uint32_t)(kk * 4096 + r * 32 + ((lg ^ ((r >> 2) & 1)) * 16));
                LDSM_X4(b_hi[ni], stg + G_WHI + off);
                LDSM_X4(b_lo[ni], stg + G_WLO + off);
            }
            // term-major: 8 independent accs between same-acc reuses
            #pragma unroll
            for (int mi = 0; mi < 2; mi++)
                #pragma unroll
                for (int nj = 0; nj < 4; nj++) {
                    const int ni = nj >> 1, sel = nj & 1;
                    MMAH16816(acc[mi][nj], af[mi], b_hi[ni][sel], b_hi[ni][sel + 2]);
                }
            #pragma unroll
            for (int mi = 0; mi < 2; mi++)
                #pragma unroll
                for (int nj = 0; nj < 4; nj++) {
                    const int ni = nj >> 1, sel = nj & 1;
                    MMAH16816(acc[mi][nj], af[mi], b_lo[ni][sel], b_lo[ni][sel + 2]);
                }
        }
    }

    const int qr = lane >> 2;
    const int qc = (lane & 3) * 2;
    #pragma unroll
    for (int nj = 0; nj < 4; nj++) {
        const int c = col0 + wn * 32 + nj * 8 + qc;
        const float2 bv = *(const float2*)(bias + c);
        #pragma unroll
        for (int mi = 0; mi < 2; mi++) {
            const int r = row0 + wm * 32 + mi * 16 + qr;
            // un-scale the *64 weight, add bias, then task scale
            float v0 = (acc[mi][nj][0] * INV_WS + bv.x) * scale;
            float v1 = (acc[mi][nj][1] * INV_WS + bv.y) * scale;
            float v2 = (acc[mi][nj][2] * INV_WS + bv.x) * scale;
            float v3 = (acc[mi][nj][3] * INV_WS + bv.y) * scale;
            if (mode == 0) {
                *(float2*)(Cf + (size_t)r * D_ + c)       = make_float2(v0, v1);
                *(float2*)(Cf + (size_t)(r + 8) * D_ + c) = make_float2(v2, v3);
            } else if (z == 0) {
                *(uint32_t*)(Cq + (size_t)r * D_ + c)       = pack_h2(v0, v1);
                *(uint32_t*)(Cq + (size_t)(r + 8) * D_ + c) = pack_h2(v2, v3);
            } else {
                uint32_t h0, l0, h1, l1;
                split_pack_h(v0, v1, h0, l0);
                split_pack_h(v2, v3, h1, l1);
                *(uint32_t*)(Chi + (size_t)r * D_ + c)       = h0;
                *(uint32_t*)(Clo + (size_t)r * D_ + c)       = l0;
                *(uint32_t*)(Chi + (size_t)(r + 8) * D_ + c) = h1;
                *(uint32_t*)(Clo + (size_t)(r + 8) * D_ + c) = l1;
            }
        }
    }
}

// ============================================================================
// Tensor-core flash attention v4 (causal), 2-term fp16.
// Q single fp16 in registers; K/V hi/lo in smem; P single fp16 from regs.
// CTA: 128 q-rows x 1 head, 8 warps, 64-key tiles, 2-stage double buffer.
// ============================================================================
#define FQ    128
#define FKT   64
#define F_KHI 0
#define F_KLO 8192
#define F_VHI 16384
#define F_VLO 24576
#define F_STG 32768
#define FSM_BYTES (2 * F_STG + 128)

__global__ __launch_bounds__(256, 2) void flash_mma(
    const __half* __restrict__ Qf,
    const __half* __restrict__ Khi, const __half* __restrict__ Klo,
    const __half* __restrict__ Vhi, const __half* __restrict__ Vlo,
    __half* __restrict__ Of)
{
    extern __shared__ char dsm[];
    const uint32_t smbase = (smem_u32(dsm) + 127u) & ~127u;

    const int tid  = threadIdx.x;
    const int lane = tid & 31;
    const int w    = tid >> 5;
    const int qb   = (int)gridDim.x - 1 - (int)blockIdx.x;  // big tiles first
    const int h    = blockIdx.y;
    const int b    = blockIdx.z;
    const int q0   = qb * FQ;

    // ---- stage Q (single, 16KB) into stage0 temporarily
    #pragma unroll
    for (int t = 0; t < 4; t++) {
        int idx = tid + t * 256;
        int row = idx >> 3, g = idx & 7;
        const __half* src = Qf + (size_t)(b * S_ + q0 + row) * D_ + h * DK_ + g * 8;
        CP_ASYNC16(smbase + row * 128 + ((g ^ (row & 7)) << 4), src);
    }
    CP_COMMIT();
    CP_WAIT0();
    __syncthreads();

    uint32_t qa[4][4];
    const int qrow = w * 16 + (lane & 15);
    const int qlg  = lane >> 4;
    #pragma unroll
    for (int c = 0; c < 4; c++) {
        uint32_t off = qrow * 128 + ((c * 32 + qlg * 16) ^ ((qrow & 7) << 4));
        LDSM_X4(qa[c], smbase + off);
    }
    __syncthreads();   // stage0 free for KV

    const __half* kvsrc[4] = {Khi, Klo, Vhi, Vlo};
    auto load_kv = [&](int t) {
        const uint32_t stg = smbase + (uint32_t)(t & 1) * F_STG;
        #pragma unroll
        for (int u = 0; u < 8; u++) {
            int idx = tid + u * 256;
            int mat = idx >> 9;
            int i   = idx & 511;
            int row = i >> 3, g = i & 7;
            const __half* src = kvsrc[mat] +
                (size_t)(b * S_ + t * FKT + row) * D_ + h * DK_ + g * 8;
            CP_ASYNC16(stg + mat * 8192 + row * 128 + ((g ^ (row & 7)) << 4), src);
        }
    };

    const int nkt = 2 * (qb + 1);
    load_kv(0); CP_COMMIT();
    if (nkt > 1) { load_kv(1); CP_COMMIT(); }

    float m_r[2] = {-1e30f, -1e30f};
    float l_r[2] = {0.0f, 0.0f};
    float oacc[8][4];
    #pragma unroll
    for (int j = 0; j < 8; j++)
        #pragma unroll
        for (int e = 0; e < 4; e++) oacc[j][e] = 0.0f;

    const int rg0 = q0 + w * 16 + (lane >> 2);

    for (int t = 0; t < nkt; t++) {
        if (t + 1 < nkt) { CP_WAIT1(); } else { CP_WAIT0(); }
        __syncthreads();

        const uint32_t stg = smbase + (uint32_t)(t & 1) * F_STG;

        // ---- scores S = Q K^T, 2-term (K hi/lo)
        float sacc[8][4];
        #pragma unroll
        for (int j = 0; j < 8; j++)
            #pragma unroll
            for (int e = 0; e < 4; e++) sacc[j][e] = 0.0f;

        #pragma unroll
        for (int c = 0; c < 4; c++) {
            #pragma unroll
            for (int ng = 0; ng < 4; ng++) {
                int row = ng * 16 + (lane & 15);
                int colb = c * 32 + qlg * 16;
                uint32_t off = row * 128 + (colb ^ ((row & 7) << 4));
                uint32_t kh[4], kl[4];
                LDSM_X4(kh, stg + F_KHI + off);
                LDSM_X4(kl, stg + F_KLO + off);
                const int j0 = ng * 2, j1 = ng * 2 + 1;
                MMAH16816(sacc[j0], qa[c], kh[0], kh[2]);
                MMAH16816(sacc[j1], qa[c], kh[1], kh[3]);
                MMAH16816(sacc[j0], qa[c], kl[0], kl[2]);
                MMAH16816(sacc[j1], qa[c], kl[1], kl[3]);
            }
        }

        // ---- causal mask
        const int kt0 = t * FKT;
        if (kt0 + FKT - 1 > q0 + w * 16) {
            #pragma unroll
            for (int j = 0; j < 8; j++) {
                int kc = kt0 + j * 8 + (lane & 3) * 2;
                if (kc     > rg0)     sacc[j][0] = -1e30f;
                if (kc + 1 > rg0)     sacc[j][1] = -1e30f;
                if (kc     > rg0 + 8) sacc[j][2] = -1e30f;
                if (kc + 1 > rg0 + 8) sacc[j][3] = -1e30f;
            }
        }

        // ---- online softmax
        float tm0 = -1e30f, tm1 = -1e30f;
        #pragma unroll
        for (int j = 0; j < 8; j++) {
            tm0 = fmaxf(tm0, fmaxf(sacc[j][0], sacc[j][1]));
            tm1 = fmaxf(tm1, fmaxf(sacc[j][2], sacc[j][3]));
        }
        tm0 = fmaxf(tm0, __shfl_xor_sync(0xffffffffu, tm0, 1));
        tm0 = fmaxf(tm0, __shfl_xor_sync(0xffffffffu, tm0, 2));
        tm1 = fmaxf(tm1, __shfl_xor_sync(0xffffffffu, tm1, 1));
        tm1 = fmaxf(tm1, __shfl_xor_sync(0xffffffffu, tm1, 2));

        float mn0 = fmaxf(m_r[0], tm0);
        float mn1 = fmaxf(m_r[1], tm1);
        float a0 = __expf(m_r[0] - mn0);
        float a1 = __expf(m_r[1] - mn1);
        m_r[0] = mn0; m_r[1] = mn1;

        float ps0 = 0.0f, ps1 = 0.0f;
        #pragma unroll
        for (int j = 0; j < 8; j++) {
            sacc[j][0] = __expf(sacc[j][0] - mn0);
            sacc[j][1] = __expf(sacc[j][1] - mn0);
            sacc[j][2] = __expf(sacc[j][2] - mn1);
            sacc[j][3] = __expf(sacc[j][3] - mn1);
            ps0 += sacc[j][0] + sacc[j][1];
            ps1 += sacc[j][2] + sacc[j][3];
        }
        ps0 += __shfl_xor_sync(0xffffffffu, ps0, 1);
        ps0 += __shfl_xor_sync(0xffffffffu, ps0, 2);
        ps1 += __shfl_xor_sync(0xffffffffu, ps1, 1);
        ps1 += __shfl_xor_sync(0xffffffffu, ps1, 2);
        l_r[0] = l_r[0] * a0 + ps0;
        l_r[1] = l_r[1] * a1 + ps1;

        #pragma unroll
        for (int j = 0; j < 8; j++) {
            oacc[j][0] *= a0; oacc[j][1] *= a0;
            oacc[j][2] *= a1; oacc[j][3] *= a1;
        }

        // ---- PV: oacc += P @ V, P single fp16, V hi/lo
        #pragma unroll
        for (int tk = 0; tk < 4; tk++) {
            uint32_t pa[4];
            pa[0] = pack_h2(sacc[2*tk][0],   sacc[2*tk][1]);
            pa[1] = pack_h2(sacc[2*tk][2],   sacc[2*tk][3]);
            pa[2] = pack_h2(sacc[2*tk+1][0], sacc[2*tk+1][1]);
            pa[3] = pack_h2(sacc[2*tk+1][2], sacc[2*tk+1][3]);

            #pragma unroll
            for (int dp = 0; dp < 4; dp++) {
                int sub = lane >> 3, i8 = lane & 7;
                int row = tk * 16 + (sub & 1) * 8 + i8;
                int colb = dp * 32 + (sub >> 1) * 16;
                uint32_t off = row * 128 + (colb ^ ((row & 7) << 4));
                uint32_t vh[4], vl[4];
                LDSM_X4_T(vh, stg + F_VHI + off);
                LDSM_X4_T(vl, stg + F_VLO + off);
                const int j0 = dp * 2, j1 = dp * 2 + 1;
                MMAH16816(oacc[j0], pa, vh[0], vh[1]);
                MMAH16816(oacc[j1], pa, vh[2], vh[3]);
                MMAH16816(oacc[j0], pa, vl[0], vl[1]);
                MMAH16816(oacc[j1], pa, vl[2], vl[3]);
            }
        }
        __syncthreads();          // all warps done with stage (t&1)
        if (t + 2 < nkt) { load_kv(t + 2); CP_COMMIT(); }
    }

    // ---- epilogue: normalize, single fp16 out
    const float inv0 = 1.0f / l_r[0];
    const float inv1 = 1.0f / l_r[1];
    const size_t r0 = (size_t)(b * S_) + rg0;
    const size_t r1 = r0 + 8;
    #pragma unroll
    for (int j = 0; j < 8; j++) {
        int col = h * DK_ + j * 8 + (lane & 3) * 2;
        *(uint32_t*)(Of + r0 * D_ + col) = pack_h2(oacc[j][0] * inv0, oacc[j][1] * inv0);
        *(uint32_t*)(Of + r1 * D_ + col) = pack_h2(oacc[j][2] * inv1, oacc[j][3] * inv1);
    }
}

// ============================================================================
// Launch
// ============================================================================
extern "C" void kernel_launch(void* const* d_in, const int* in_sizes, int n_in,
                              void* d_out, int out_size)
{
    const float* X  = (const float*)d_in[0];
    const float* Wq = (const float*)d_in[1];
    const float* bq = (const float*)d_in[2];
    const float* Wk = (const float*)d_in[3];
    const float* bk = (const float*)d_in[4];
    const float* Wv = (const float*)d_in[5];
    const float* bv = (const float*)d_in[6];
    const float* Wo = (const float*)d_in[7];
    const float* bo = (const float*)d_in[8];
    float* out = (float*)d_out;

    __half *xf, *wh, *wl, *qf, *kh, *kl, *vh, *vl, *of;
    cudaGetSymbolAddress((void**)&xf, g_xf);
    cudaGetSymbolAddress((void**)&wh, g_wh);
    cudaGetSymbolAddress((void**)&wl, g_wl);
    cudaGetSymbolAddress((void**)&qf, g_qf);
    cudaGetSymbolAddress((void**)&kh, g_kh);
    cudaGetSymbolAddress((void**)&kl, g_kl);
    cudaGetSymbolAddress((void**)&vh, g_vh);
    cudaGetSymbolAddress((void**)&vl, g_vl);
    cudaGetSymbolAddress((void**)&of, g_of);

    cudaFuncSetAttribute(gemm_mma, cudaFuncAttributeMaxDynamicSharedMemorySize, GSM_BYTES);
    cudaFuncSetAttribute(flash_mma, cudaFuncAttributeMaxDynamicSharedMemorySize, FSM_BYTES);

    const int nX = MTOT * D_;
    const int nW = D_ * D_;

    cvt_half<<<nX / 1024, 256>>>(X, xf, nX);
    split_w4<<<dim3(nW / 1024, 1, 4), 256>>>(Wq, Wk, Wv, Wo, wh, wl);

    // fused QKV projection (z = 0:Q single-scaled, 1:K hi/lo, 2:V hi/lo)
    gemm_mma<<<dim3(8, 64, 3), 256, GSM_BYTES>>>(
        xf, wh, wl, 0, bq, bk, bv,
        nullptr, qf, kh, kl, vh, vl, 0.125f, 1);

    flash_mma<<<dim3(S_ / FQ, H_, B_), 256, FSM_BYTES>>>(qf, kh, kl, vh, vl, of);

    // O projection (fp32 out)
    gemm_mma<<<dim3(8, 64, 1), 256, GSM_BYTES>>>(
        of, wh, wl, 3, bo, bo, bo,
        out, nullptr, nullptr, nullptr, nullptr, nullptr, 1.0f, 0);
}

// round 9
// speedup vs baseline: 2.6380x; 1.9199x over previous
#include <cuda_runtime.h>
#include <cuda_fp16.h>
#include <math.h>
#include <stdint.h>

// Problem constants
#define B_   2
#define S_   2048
#define D_   1024
#define H_   16
#define DK_  64
#define MTOT (B_ * S_)   // 4096
#define WSZ  ((size_t)D_ * D_)

#define WSCALE   64.0f
#define INV_WS   (1.0f / 64.0f)

// fp16 buffers (all single precision fp16, fp32 accumulate in MMA)
__device__ __half g_xf [(size_t)MTOT * D_];     // X
__device__ __half g_wf [4][WSZ];                // 64*W
__device__ __half g_qf [(size_t)MTOT * D_];     // Q (pre-scaled by 1/8)
__device__ __half g_kf [(size_t)MTOT * D_];
__device__ __half g_vf [(size_t)MTOT * D_];
__device__ __half g_of [(size_t)MTOT * D_];     // attn out

// ============================================================================
// PTX helpers (base sm_100-safe)
// ============================================================================
__device__ __forceinline__ uint32_t smem_u32(const void* p) {
    return (uint32_t)__cvta_generic_to_shared(p);
}

#define CP_ASYNC16(dst, src) \
    asm volatile("cp.async.cg.shared.global [%0], [%1], 16;" :: "r"(dst), "l"(src))
#define CP_COMMIT() asm volatile("cp.async.commit_group;")
#define CP_WAIT1()  asm volatile("cp.async.wait_group 1;")
#define CP_WAIT0()  asm volatile("cp.async.wait_group 0;")

#define LDSM_X4(r, addr)                                                     \
    asm volatile("ldmatrix.sync.aligned.m8n8.x4.shared.b16 {%0,%1,%2,%3}, [%4];" \
                 : "=r"((r)[0]), "=r"((r)[1]), "=r"((r)[2]), "=r"((r)[3])    \
                 : "r"(addr))

#define LDSM_X4_T(r, addr)                                                   \
    asm volatile("ldmatrix.sync.aligned.m8n8.x4.trans.shared.b16 {%0,%1,%2,%3}, [%4];" \
                 : "=r"((r)[0]), "=r"((r)[1]), "=r"((r)[2]), "=r"((r)[3])    \
                 : "r"(addr))

#define MMAH16816(d, a, b0v, b1v)                                            \
    asm volatile("mma.sync.aligned.m16n8k16.row.col.f32.f16.f16.f32 "       \
                 "{%0,%1,%2,%3}, {%4,%5,%6,%7}, {%8,%9}, {%0,%1,%2,%3};"    \
                 : "+f"((d)[0]), "+f"((d)[1]), "+f"((d)[2]), "+f"((d)[3])   \
                 : "r"((a)[0]), "r"((a)[1]), "r"((a)[2]), "r"((a)[3]),      \
                   "r"(b0v), "r"(b1v))

__device__ __forceinline__ uint32_t pack_h2(float a, float b) {
    __half2 h = __floats2half2_rn(a, b);
    return *(uint32_t*)&h;
}

// ============================================================================
// conversion kernels
// ============================================================================
__global__ void cvt_half(const float* __restrict__ src, __half* __restrict__ dst, int n)
{
    int i = (blockIdx.x * blockDim.x + threadIdx.x) * 4;
    if (i >= n) return;
    float4 v = *(const float4*)(src + i);
    uint2 o = make_uint2(pack_h2(v.x, v.y), pack_h2(v.z, v.w));
    *(uint2*)(dst + i) = o;
}

// 4-weight convert with *WSCALE pre-scaling (z selects which W)
__global__ void cvt_w4(const float* __restrict__ W0, const float* __restrict__ W1,
                       const float* __restrict__ W2, const float* __restrict__ W3,
                       __half* __restrict__ dstB)
{
    const int z = blockIdx.z;
    const float* src = (z == 0) ? W0 : (z == 1) ? W1 : (z == 2) ? W2 : W3;
    int i = (blockIdx.x * blockDim.x + threadIdx.x) * 4;
    float4 v = *(const float4*)(src + i);
    uint2 o = make_uint2(pack_h2(v.x * WSCALE, v.y * WSCALE),
                         pack_h2(v.z * WSCALE, v.w * WSCALE));
    *(uint2*)(dstB + z * WSZ + i) = o;
}

// ============================================================================
// mma.sync GEMM v5: C = A @ W^T + bias   (pure fp16, fp32 acc)
// CTA 64x128, 8 warps 2(m)x4(n), warp tile 32x32, BK=32, 3-stage pipeline.
// Stage 12KB: A(4KB) | W(8KB).
// ============================================================================
#define GBK     32
#define G_A     0u
#define G_W     4096u
#define G_STAGE 12288u
#define GSM_BYTES (3 * 12288 + 128)

__global__ __launch_bounds__(256, 2) void gemm_mma(
    const __half* __restrict__ Af,
    const __half* __restrict__ WfB,
    int wofs,
    const float* __restrict__ b0, const float* __restrict__ b1, const float* __restrict__ b2,
    float* __restrict__ Cf,
    __half* __restrict__ C0, __half* __restrict__ C1, __half* __restrict__ C2,
    float qs, int mode)
{
    extern __shared__ char dsm[];
    const uint32_t smbase = (smem_u32(dsm) + 127u) & ~127u;

    const int tid  = threadIdx.x;
    const int lane = tid & 31;
    const int wid  = tid >> 5;
    const int wm   = wid >> 2;      // 0..1
    const int wn   = wid & 3;       // 0..3
    const int row0 = blockIdx.y * 64;
    const int col0 = blockIdx.x * 128;
    const int z    = blockIdx.z;

    const __half* Wf = WfB + (size_t)(wofs + z) * WSZ;
    const float* bias = (z == 0) ? b0 : (z == 1) ? b1 : b2;
    __half* Ch = (z == 0) ? C0 : (z == 1) ? C1 : C2;
    const float scale = (z == 0) ? qs : 1.0f;

    const __half* srcs[2] = { Af + (size_t)row0 * D_, Wf + (size_t)col0 * D_ };

    // loader: 768 granules/stage (A:256, W:512) = 3/thread
    int l_mat[3], l_r[3], l_koff[3];
    uint32_t l_dst[3];
    #pragma unroll
    for (int t = 0; t < 3; t++) {
        int idx = tid + t * 256;
        int mat, i;
        uint32_t base, chunk;
        if (idx < 256) { mat = 0; i = idx;       base = G_A; chunk = 2048u; }
        else           { mat = 1; i = idx - 256; base = G_W; chunk = 4096u; }
        int r = i >> 2, kk = (i >> 1) & 1, g = i & 1;
        int gsw = g ^ ((r >> 2) & 1);
        l_mat[t] = mat; l_r[t] = r; l_koff[t] = kk * 16 + g * 8;
        l_dst[t] = base + (uint32_t)kk * chunk + (uint32_t)r * 32u + (uint32_t)gsw * 16u;
    }

    auto issue = [&](int it2) {
        const uint32_t sb = smbase + (uint32_t)(it2 % 3) * G_STAGE;
        #pragma unroll
        for (int t = 0; t < 3; t++) {
            const __half* gp = srcs[l_mat[t]] +
                (size_t)l_r[t] * D_ + it2 * GBK + l_koff[t];
            CP_ASYNC16(sb + l_dst[t], gp);
        }
    };

    float acc[2][4][4];
    #pragma unroll
    for (int mi = 0; mi < 2; mi++)
        #pragma unroll
        for (int nj = 0; nj < 4; nj++)
            #pragma unroll
            for (int e = 0; e < 4; e++) acc[mi][nj][e] = 0.0f;

    const int lr = lane & 15;
    const int lg = lane >> 4;

    issue(0); CP_COMMIT();
    issue(1); CP_COMMIT();

    const int NIT = D_ / GBK;   // 32
    for (int it = 0; it < NIT; it++) {
        if (it < NIT - 1) { CP_WAIT1(); } else { CP_WAIT0(); }
        __syncthreads();
        if (it + 2 < NIT) { issue(it + 2); CP_COMMIT(); }

        const uint32_t stg = smbase + (uint32_t)(it % 3) * G_STAGE;
        #pragma unroll
        for (int kk = 0; kk < 2; kk++) {
            uint32_t af[2][4];
            #pragma unroll
            for (int mi = 0; mi < 2; mi++) {
                int r = wm * 32 + mi * 16 + lr;
                uint32_t off = (uint32_t)(kk * 2048 + r * 32 + ((lg ^ ((r >> 2) & 1)) * 16));
                LDSM_X4(af[mi], stg + G_A + off);
            }
            uint32_t bw[2][4];
            #pragma unroll
            for (int ni = 0; ni < 2; ni++) {
                int r = wn * 32 + ni * 16 + lr;
                uint32_t off = (uint32_t)(kk * 4096 + r * 32 + ((lg ^ ((r >> 2) & 1)) * 16));
                LDSM_X4(bw[ni], stg + G_W + off);
            }
            // 8 independent accumulators
            #pragma unroll
            for (int mi = 0; mi < 2; mi++)
                #pragma unroll
                for (int nj = 0; nj < 4; nj++) {
                    const int ni = nj >> 1, sel = nj & 1;
                    MMAH16816(acc[mi][nj], af[mi], bw[ni][sel], bw[ni][sel + 2]);
                }
        }
    }

    const int qr = lane >> 2;
    const int qc = (lane & 3) * 2;
    #pragma unroll
    for (int nj = 0; nj < 4; nj++) {
        const int c = col0 + wn * 32 + nj * 8 + qc;
        const float2 bv = *(const float2*)(bias + c);
        #pragma unroll
        for (int mi = 0; mi < 2; mi++) {
            const int r = row0 + wm * 32 + mi * 16 + qr;
            float v0 = (acc[mi][nj][0] * INV_WS + bv.x) * scale;
            float v1 = (acc[mi][nj][1] * INV_WS + bv.y) * scale;
            float v2 = (acc[mi][nj][2] * INV_WS + bv.x) * scale;
            float v3 = (acc[mi][nj][3] * INV_WS + bv.y) * scale;
            if (mode == 0) {
                *(float2*)(Cf + (size_t)r * D_ + c)       = make_float2(v0, v1);
                *(float2*)(Cf + (size_t)(r + 8) * D_ + c) = make_float2(v2, v3);
            } else {
                *(uint32_t*)(Ch + (size_t)r * D_ + c)       = pack_h2(v0, v1);
                *(uint32_t*)(Ch + (size_t)(r + 8) * D_ + c) = pack_h2(v2, v3);
            }
        }
    }
}

// ============================================================================
// Tensor-core flash attention v5 (causal), pure fp16 (fp32 acc).
// CTA: 128 q-rows x 1 head, 8 warps, 64-key tiles, 2-stage double buffer.
// Stage 16KB: K(8KB) | V(8KB).
// ============================================================================
#define FQ    128
#define FKT   64
#define F_K   0
#define F_V   8192
#define F_STG 16384
#define FSM_BYTES (2 * F_STG + 128)

__global__ __launch_bounds__(256, 2) void flash_mma(
    const __half* __restrict__ Qf,
    const __half* __restrict__ Kf, const __half* __restrict__ Vf,
    __half* __restrict__ Of)
{
    extern __shared__ char dsm[];
    const uint32_t smbase = (smem_u32(dsm) + 127u) & ~127u;

    const int tid  = threadIdx.x;
    const int lane = tid & 31;
    const int w    = tid >> 5;
    const int qb   = (int)gridDim.x - 1 - (int)blockIdx.x;  // big tiles first
    const int h    = blockIdx.y;
    const int b    = blockIdx.z;
    const int q0   = qb * FQ;

    // ---- stage Q (16KB) into stage0 temporarily
    #pragma unroll
    for (int t = 0; t < 4; t++) {
        int idx = tid + t * 256;
        int row = idx >> 3, g = idx & 7;
        const __half* src = Qf + (size_t)(b * S_ + q0 + row) * D_ + h * DK_ + g * 8;
        CP_ASYNC16(smbase + row * 128 + ((g ^ (row & 7)) << 4), src);
    }
    CP_COMMIT();
    CP_WAIT0();
    __syncthreads();

    uint32_t qa[4][4];
    const int qrow = w * 16 + (lane & 15);
    const int qlg  = lane >> 4;
    #pragma unroll
    for (int c = 0; c < 4; c++) {
        uint32_t off = qrow * 128 + ((c * 32 + qlg * 16) ^ ((qrow & 7) << 4));
        LDSM_X4(qa[c], smbase + off);
    }
    __syncthreads();   // stage0 free for KV

    auto load_kv = [&](int t) {
        const uint32_t stg = smbase + (uint32_t)(t & 1) * F_STG;
        #pragma unroll
        for (int u = 0; u < 4; u++) {
            int idx = tid + u * 256;
            int mat = idx >> 9;            // 0=K, 1=V
            int i   = idx & 511;
            int row = i >> 3, g = i & 7;
            const __half* src = (mat ? Vf : Kf) +
                (size_t)(b * S_ + t * FKT + row) * D_ + h * DK_ + g * 8;
            CP_ASYNC16(stg + mat * 8192 + row * 128 + ((g ^ (row & 7)) << 4), src);
        }
    };

    const int nkt = 2 * (qb + 1);
    load_kv(0); CP_COMMIT();
    if (nkt > 1) { load_kv(1); CP_COMMIT(); }

    float m_r[2] = {-1e30f, -1e30f};
    float l_r[2] = {0.0f, 0.0f};
    float oacc[8][4];
    #pragma unroll
    for (int j = 0; j < 8; j++)
        #pragma unroll
        for (int e = 0; e < 4; e++) oacc[j][e] = 0.0f;

    const int rg0 = q0 + w * 16 + (lane >> 2);

    for (int t = 0; t < nkt; t++) {
        if (t + 1 < nkt) { CP_WAIT1(); } else { CP_WAIT0(); }
        __syncthreads();

        const uint32_t stg = smbase + (uint32_t)(t & 1) * F_STG;

        // ---- scores S = Q K^T
        float sacc[8][4];
        #pragma unroll
        for (int j = 0; j < 8; j++)
            #pragma unroll
            for (int e = 0; e < 4; e++) sacc[j][e] = 0.0f;

        #pragma unroll
        for (int c = 0; c < 4; c++) {
            #pragma unroll
            for (int ng = 0; ng < 4; ng++) {
                int row = ng * 16 + (lane & 15);
                int colb = c * 32 + qlg * 16;
                uint32_t off = row * 128 + (colb ^ ((row & 7) << 4));
                uint32_t kh[4];
                LDSM_X4(kh, stg + F_K + off);
                const int j0 = ng * 2, j1 = ng * 2 + 1;
                MMAH16816(sacc[j0], qa[c], kh[0], kh[2]);
                MMAH16816(sacc[j1], qa[c], kh[1], kh[3]);
            }
        }

        // ---- causal mask
        const int kt0 = t * FKT;
        if (kt0 + FKT - 1 > q0 + w * 16) {
            #pragma unroll
            for (int j = 0; j < 8; j++) {
                int kc = kt0 + j * 8 + (lane & 3) * 2;
                if (kc     > rg0)     sacc[j][0] = -1e30f;
                if (kc + 1 > rg0)     sacc[j][1] = -1e30f;
                if (kc     > rg0 + 8) sacc[j][2] = -1e30f;
                if (kc + 1 > rg0 + 8) sacc[j][3] = -1e30f;
            }
        }

        // ---- online softmax
        float tm0 = -1e30f, tm1 = -1e30f;
        #pragma unroll
        for (int j = 0; j < 8; j++) {
            tm0 = fmaxf(tm0, fmaxf(sacc[j][0], sacc[j][1]));
            tm1 = fmaxf(tm1, fmaxf(sacc[j][2], sacc[j][3]));
        }
        tm0 = fmaxf(tm0, __shfl_xor_sync(0xffffffffu, tm0, 1));
        tm0 = fmaxf(tm0, __shfl_xor_sync(0xffffffffu, tm0, 2));
        tm1 = fmaxf(tm1, __shfl_xor_sync(0xffffffffu, tm1, 1));
        tm1 = fmaxf(tm1, __shfl_xor_sync(0xffffffffu, tm1, 2));

        float mn0 = fmaxf(m_r[0], tm0);
        float mn1 = fmaxf(m_r[1], tm1);
        float a0 = __expf(m_r[0] - mn0);
        float a1 = __expf(m_r[1] - mn1);
        m_r[0] = mn0; m_r[1] = mn1;

        float ps0 = 0.0f, ps1 = 0.0f;
        #pragma unroll
        for (int j = 0; j < 8; j++) {
            sacc[j][0] = __expf(sacc[j][0] - mn0);
            sacc[j][1] = __expf(sacc[j][1] - mn0);
            sacc[j][2] = __expf(sacc[j][2] - mn1);
            sacc[j][3] = __expf(sacc[j][3] - mn1);
            ps0 += sacc[j][0] + sacc[j][1];
            ps1 += sacc[j][2] + sacc[j][3];
        }
        ps0 += __shfl_xor_sync(0xffffffffu, ps0, 1);
        ps0 += __shfl_xor_sync(0xffffffffu, ps0, 2);
        ps1 += __shfl_xor_sync(0xffffffffu, ps1, 1);
        ps1 += __shfl_xor_sync(0xffffffffu, ps1, 2);
        l_r[0] = l_r[0] * a0 + ps0;
        l_r[1] = l_r[1] * a1 + ps1;

        #pragma unroll
        for (int j = 0; j < 8; j++) {
            oacc[j][0] *= a0; oacc[j][1] *= a0;
            oacc[j][2] *= a1; oacc[j][3] *= a1;
        }

        // ---- PV: oacc += P @ V
        #pragma unroll
        for (int tk = 0; tk < 4; tk++) {
            uint32_t pa[4];
            pa[0] = pack_h2(sacc[2*tk][0],   sacc[2*tk][1]);
            pa[1] = pack_h2(sacc[2*tk][2],   sacc[2*tk][3]);
            pa[2] = pack_h2(sacc[2*tk+1][0], sacc[2*tk+1][1]);
            pa[3] = pack_h2(sacc[2*tk+1][2], sacc[2*tk+1][3]);

            #pragma unroll
            for (int dp = 0; dp < 4; dp++) {
                int sub = lane >> 3, i8 = lane & 7;
                int row = tk * 16 + (sub & 1) * 8 + i8;
                int colb = dp * 32 + (sub >> 1) * 16;
                uint32_t off = row * 128 + (colb ^ ((row & 7) << 4));
                uint32_t vh[4];
                LDSM_X4_T(vh, stg + F_V + off);
                const int j0 = dp * 2, j1 = dp * 2 + 1;
                MMAH16816(oacc[j0], pa, vh[0], vh[1]);
                MMAH16816(oacc[j1], pa, vh[2], vh[3]);
            }
        }
        __syncthreads();          // all warps done with stage (t&1)
        if (t + 2 < nkt) { load_kv(t + 2); CP_COMMIT(); }
    }

    // ---- epilogue: normalize, fp16 out
    const float inv0 = 1.0f / l_r[0];
    const float inv1 = 1.0f / l_r[1];
    const size_t r0 = (size_t)(b * S_) + rg0;
    const size_t r1 = r0 + 8;
    #pragma unroll
    for (int j = 0; j < 8; j++) {
        int col = h * DK_ + j * 8 + (lane & 3) * 2;
        *(uint32_t*)(Of + r0 * D_ + col) = pack_h2(oacc[j][0] * inv0, oacc[j][1] * inv0);
        *(uint32_t*)(Of + r1 * D_ + col) = pack_h2(oacc[j][2] * inv1, oacc[j][3] * inv1);
    }
}

// ============================================================================
// Launch
// ============================================================================
extern "C" void kernel_launch(void* const* d_in, const int* in_sizes, int n_in,
                              void* d_out, int out_size)
{
    const float* X  = (const float*)d_in[0];
    const float* Wq = (const float*)d_in[1];
    const float* bq = (const float*)d_in[2];
    const float* Wk = (const float*)d_in[3];
    const float* bk = (const float*)d_in[4];
    const float* Wv = (const float*)d_in[5];
    const float* bv = (const float*)d_in[6];
    const float* Wo = (const float*)d_in[7];
    const float* bo = (const float*)d_in[8];
    float* out = (float*)d_out;

    __half *xf, *wf, *qf, *kf, *vf, *of;
    cudaGetSymbolAddress((void**)&xf, g_xf);
    cudaGetSymbolAddress((void**)&wf, g_wf);
    cudaGetSymbolAddress((void**)&qf, g_qf);
    cudaGetSymbolAddress((void**)&kf, g_kf);
    cudaGetSymbolAddress((void**)&vf, g_vf);
    cudaGetSymbolAddress((void**)&of, g_of);

    cudaFuncSetAttribute(gemm_mma, cudaFuncAttributeMaxDynamicSharedMemorySize, GSM_BYTES);
    cudaFuncSetAttribute(flash_mma, cudaFuncAttributeMaxDynamicSharedMemorySize, FSM_BYTES);

    const int nX = MTOT * D_;
    const int nW = D_ * D_;

    cvt_half<<<nX / 1024, 256>>>(X, xf, nX);
    cvt_w4<<<dim3(nW / 1024, 1, 4), 256>>>(Wq, Wk, Wv, Wo, wf);

    // fused QKV projection (z = 0:Q scaled, 1:K, 2:V)
    gemm_mma<<<dim3(8, 64, 3), 256, GSM_BYTES>>>(
        xf, wf, 0, bq, bk, bv,
        nullptr, qf, kf, vf, 0.125f, 1);

    flash_mma<<<dim3(S_ / FQ, H_, B_), 256, FSM_BYTES>>>(qf, kf, vf, of);

    // O projection (fp32 out)
    gemm_mma<<<dim3(8, 64, 1), 256, GSM_BYTES>>>(
        of, wf, 3, bo, bo, bo,
        out, nullptr, nullptr, nullptr, 1.0f, 0);
}